// round 15
// baseline (speedup 1.0000x reference)
#include <cuda_runtime.h>
#include <cstdint>
#include <math.h>

#define D_MODEL     2048
#define NUM_EXPERTS 64
#define N_TOKENS    16384
#define BM          64                  // tokens per CTA (4 warps x 16 tokens)
#define BK          32                  // K per chunk
#define NCHUNK      (D_MODEL / BK)      // 64
#define THREADS     128
#define GAP_THRESH  3e-4f
#define LSTRIDE     65

// pre-converted W planes: [chunk][expert][pair] = uint2{plane1 bf16x2, plane2 bf16x2}
__device__ uint2 gWB[NCHUNK * NUM_EXPERTS * 16];

// ---------------------------------------------------------------------------
static __device__ __forceinline__ uint32_t bf16x2_rn(float lo, float hi) {
    uint32_t r;
    asm("cvt.rn.bf16x2.f32 %0, %1, %2;" : "=r"(r) : "f"(hi), "f"(lo));
    return r;
}
static __device__ __forceinline__ float bf16_lo_f(uint32_t u) {
    return __uint_as_float(u << 16);
}
static __device__ __forceinline__ float bf16_hi_f(uint32_t u) {
    return __uint_as_float(u & 0xffff0000u);
}
static __device__ __forceinline__ uint2 split_pair(float x, float y) {
    uint32_t b1 = bf16x2_rn(x, y);
    float r1x = x - bf16_lo_f(b1);
    float r1y = y - bf16_hi_f(b1);
    uint32_t b2 = bf16x2_rn(r1x, r1y);
    return make_uint2(b1, b2);
}
static __device__ __forceinline__ void mma_bf16(float* d,
                                                uint32_t a0, uint32_t a1,
                                                uint32_t a2, uint32_t a3,
                                                uint32_t b0, uint32_t b1) {
    asm volatile(
        "mma.sync.aligned.m16n8k16.row.col.f32.bf16.bf16.f32 "
        "{%0,%1,%2,%3}, {%4,%5,%6,%7}, {%8,%9}, {%0,%1,%2,%3};"
        : "+f"(d[0]), "+f"(d[1]), "+f"(d[2]), "+f"(d[3])
        : "r"(a0), "r"(a1), "r"(a2), "r"(a3), "r"(b0), "r"(b1));
}

// ---------------------------------------------------------------------------
// Kernel 0: convert W -> bf16 plane pairs in [chunk][expert][pair] order
// ---------------------------------------------------------------------------
__global__ void conv_w(const float* __restrict__ W) {
    int pi = blockIdx.x * 256 + threadIdx.x;          // stride over 65536 pairs
    #pragma unroll
    for (int it = 0; it < 4; it++, pi += 16384) {
        int p = pi & 15, e = (pi >> 4) & 63, c = pi >> 10;
        int k = c * BK + 2 * p;
        gWB[pi] = split_pair(W[e * D_MODEL + k], W[e * D_MODEL + k + 1]);
    }
}

// ---------------------------------------------------------------------------
// Kernel 1: smem-free register-direct bf16x3 GEMM + top-4 gap test +
// in-CTA fp64 refinement. No barriers in the mainloop.
// ---------------------------------------------------------------------------
__global__ __launch_bounds__(THREADS)
void router_fused(const float* __restrict__ X, const float* __restrict__ W,
                  const float* __restrict__ bias, float* __restrict__ out) {
    __shared__ float bias_s[NUM_EXPERTS];
    __shared__ float L[BM * LSTRIDE];
    __shared__ int   flags[1 + BM * 5];

    const int tid  = threadIdx.x;
    const int wid  = tid >> 5;
    const int lane = tid & 31;
    const int grp  = lane >> 2;     // 0..7
    const int qid  = lane & 3;      // 0..3
    const int token0 = blockIdx.x * BM;
    const int r0 = wid * 16 + grp;  // warp tile: 16 tokens x 64 experts

    if (tid < NUM_EXPERTS) bias_s[tid] = bias[tid];
    if (tid == 0) flags[0] = 0;

    const float* xRow0 = X + (size_t)(token0 + r0) * D_MODEL;
    const float* xRow1 = X + (size_t)(token0 + r0 + 8) * D_MODEL;

    float acc[8][4];
    #pragma unroll
    for (int n = 0; n < 8; n++)
        #pragma unroll
        for (int r = 0; r < 4; r++) acc[n][r] = 0.0f;

    // A register double-buffer, 2 chunks deep.
    // aReg[b][j]: j=0..3 -> row r0, pairs qid+4j ; j=4..7 -> row r0+8
    float2 aReg[2][8];
    #pragma unroll
    for (int j = 0; j < 4; j++) {
        aReg[0][j]     = *(const float2*)(xRow0 + (qid + 4 * j) * 2);
        aReg[0][4 + j] = *(const float2*)(xRow1 + (qid + 4 * j) * 2);
        aReg[1][j]     = *(const float2*)(xRow0 + BK + (qid + 4 * j) * 2);
        aReg[1][4 + j] = *(const float2*)(xRow1 + BK + (qid + 4 * j) * 2);
    }

    #pragma unroll 1
    for (int c = 0; c < NCHUNK; c++) {
        // convert this chunk's A to planes (frees aReg[c&1] for prefetch)
        float2* ac = aReg[c & 1];
        uint2 ap[8];
        #pragma unroll
        for (int j = 0; j < 8; j++) ap[j] = split_pair(ac[j].x, ac[j].y);

        // prefetch A for chunk c+2 (DRAM, 2-chunk distance)
        if (c + 2 < NCHUNK) {
            const int k0 = (c + 2) * BK;
            #pragma unroll
            for (int j = 0; j < 4; j++) {
                ac[j]     = *(const float2*)(xRow0 + k0 + (qid + 4 * j) * 2);
                ac[4 + j] = *(const float2*)(xRow1 + k0 + (qid + 4 * j) * 2);
            }
        }

        // B fragments for both k16 slices, direct from L2 (independent loads)
        const uint2* bc = gWB + (size_t)c * (NUM_EXPERTS * 16);
        uint2 b0[2][8], b1[2][8];
        #pragma unroll
        for (int s8 = 0; s8 < 2; s8++) {
            const int p0 = s8 * 8 + qid;
            #pragma unroll
            for (int n = 0; n < 8; n++) {
                const int e = n * 8 + grp;
                b0[s8][n] = __ldg(bc + e * 16 + p0);
                b1[s8][n] = __ldg(bc + e * 16 + p0 + 4);
            }
        }

        // MMA bursts (slice fragment mapping: slice s8 uses ap[2*s8], ap[2*s8+1])
        #pragma unroll
        for (int s8 = 0; s8 < 2; s8++) {
            uint2 a0 = ap[2 * s8];          // row r0,   p0
            uint2 a1 = ap[4 + 2 * s8];      // row r0+8, p0
            uint2 a2 = ap[2 * s8 + 1];      // row r0,   p0+4
            uint2 a3 = ap[4 + 2 * s8 + 1];  // row r0+8, p0+4
            #pragma unroll
            for (int n = 0; n < 8; n++) {
                mma_bf16(acc[n], a0.x, a1.x, a2.x, a3.x, b0[s8][n].x, b1[s8][n].x); // 1*1
                mma_bf16(acc[n], a0.x, a1.x, a2.x, a3.x, b0[s8][n].y, b1[s8][n].y); // 1*2
                mma_bf16(acc[n], a0.y, a1.y, a2.y, a3.y, b0[s8][n].x, b1[s8][n].x); // 2*1
            }
        }
    }

    // ------------------------------------------------------------------
    // epilogue: stage logits, per-token top-4 scan, gap test
    // ------------------------------------------------------------------
    #pragma unroll
    for (int n = 0; n < 8; n++) {
        int e0 = n * 8 + 2 * qid;
        L[r0 * LSTRIDE + e0]           = acc[n][0];
        L[r0 * LSTRIDE + e0 + 1]       = acc[n][1];
        L[(r0 + 8) * LSTRIDE + e0]     = acc[n][2];
        L[(r0 + 8) * LSTRIDE + e0 + 1] = acc[n][3];
    }
    __syncthreads();

    if (tid < BM) {
        const float* Lr = L + tid * LSTRIDE;
        float tv0 = -1e30f, tv1 = -1e30f, tv2 = -1e30f, tv3 = -1e30f;
        int   ti0 = 0, ti1 = 0, ti2 = 0, ti3 = 0;
        #pragma unroll
        for (int e = 0; e < NUM_EXPERTS; e++) {
            float v = Lr[e] + bias_s[e];
            if (v > tv0) {
                tv3 = tv2; ti3 = ti2; tv2 = tv1; ti2 = ti1;
                tv1 = tv0; ti1 = ti0; tv0 = v;  ti0 = e;
            } else if (v > tv1) {
                tv3 = tv2; ti3 = ti2; tv2 = tv1; ti2 = ti1; tv1 = v; ti1 = e;
            } else if (v > tv2) {
                tv3 = tv2; ti3 = ti2; tv2 = v;  ti2 = e;
            } else if (v > tv3) {
                tv3 = v; ti3 = e;
            }
        }
        const int token = token0 + tid;
        if ((tv0 - tv1) < GAP_THRESH || (tv1 - tv2) < GAP_THRESH) {
            int idx = atomicAdd(&flags[0], 1);
            int* rec = &flags[1 + idx * 5];
            rec[0] = token; rec[1] = ti0; rec[2] = ti1; rec[3] = ti2; rec[4] = ti3;
        } else {
            float r  = expf(tv1 - tv0);
            out[token * 2 + 0] = 1.0f / (1.0f + r);
            out[token * 2 + 1] = r / (1.0f + r);
            out[N_TOKENS * 2 + token * 2 + 0] = (float)ti0;
            out[N_TOKENS * 2 + token * 2 + 1] = (float)ti1;
        }
    }
    __syncthreads();

    // ------------------------------------------------------------------
    // in-CTA fp64 refinement of flagged tokens (one warp per record)
    // ------------------------------------------------------------------
    const int nrec = flags[0];
    for (int r = wid; r < nrec; r += 4) {
        const int* rec = &flags[1 + r * 5];
        const int token = rec[0];
        const float* xr = X + (size_t)token * D_MODEL;
        const float* w0 = W + (size_t)rec[1] * D_MODEL;
        const float* w1 = W + (size_t)rec[2] * D_MODEL;
        const float* w2 = W + (size_t)rec[3] * D_MODEL;
        const float* w3 = W + (size_t)rec[4] * D_MODEL;

        double a0[4] = {0, 0, 0, 0}, a1[4] = {0, 0, 0, 0};
        #pragma unroll 4
        for (int k = lane; k < D_MODEL; k += 64) {
            double x0 = (double)xr[k], x1 = (double)xr[k + 32];
            a0[0] += x0 * (double)w0[k];  a1[0] += x1 * (double)w0[k + 32];
            a0[1] += x0 * (double)w1[k];  a1[1] += x1 * (double)w1[k + 32];
            a0[2] += x0 * (double)w2[k];  a1[2] += x1 * (double)w2[k + 32];
            a0[3] += x0 * (double)w3[k];  a1[3] += x1 * (double)w3[k + 32];
        }
        double lv[4];
        #pragma unroll
        for (int cc = 0; cc < 4; cc++) {
            double s = a0[cc] + a1[cc];
            #pragma unroll
            for (int off = 16; off; off >>= 1)
                s += __shfl_down_sync(0xffffffffu, s, off);
            lv[cc] = s + (double)bias_s[rec[1 + cc]];
        }
        if (lane == 0) {
            int ei[4] = {rec[1], rec[2], rec[3], rec[4]};
            #pragma unroll
            for (int i = 1; i < 4; i++) {
                double v = lv[i]; int id = ei[i];
                int j = i - 1;
                while (j >= 0 && (lv[j] < v || (lv[j] == v && ei[j] > id))) {
                    lv[j + 1] = lv[j]; ei[j + 1] = ei[j]; j--;
                }
                lv[j + 1] = v; ei[j + 1] = id;
            }
            double rr = exp(lv[1] - lv[0]);
            out[token * 2 + 0] = (float)(1.0 / (1.0 + rr));
            out[token * 2 + 1] = (float)(rr / (1.0 + rr));
            out[N_TOKENS * 2 + token * 2 + 0] = (float)ei[0];
            out[N_TOKENS * 2 + token * 2 + 1] = (float)ei[1];
        }
    }
}

// ---------------------------------------------------------------------------
extern "C" void kernel_launch(void* const* d_in, const int* in_sizes, int n_in,
                              void* d_out, int out_size) {
    const float* X = (const float*)d_in[0];   // [4, 4096, 2048]
    const float* W = (const float*)d_in[1];   // [64, 2048]
    const float* b = (const float*)d_in[2];   // [64]
    float* out = (float*)d_out;

    conv_w<<<64, 256>>>(W);
    router_fused<<<N_TOKENS / BM, THREADS>>>(X, W, b, out);
}

// round 16
// speedup vs baseline: 1.9566x; 1.9566x over previous
#include <cuda_runtime.h>
#include <cstdint>
#include <math.h>

#define D_MODEL     2048
#define NUM_EXPERTS 64
#define N_TOKENS    16384
#define BM          128                 // tokens per CTA
#define BK          32                  // K per chunk
#define NCHUNK      (D_MODEL / BK)      // 64
#define THREADS     256                 // 8 warps x 16 tokens
#define ROWB        160                 // bytes per smem row (128 data + 32 pad)
#define GAP_THRESH  3e-4f
#define LSTRIDE     65

// smem: bias 256B | double-buffered {As 128x160, Bs 64x160}
// epilogue reuse: L[128][65] floats at SM_BUF (33280B), flags after
#define SM_BIAS     0
#define SM_BUF      256
#define ASIZE       (BM * ROWB)                       // 20480
#define BUFSTRIDE   (ASIZE + NUM_EXPERTS * ROWB)      // 30720
#define SM_FLAGS    (SM_BUF + BM * LSTRIDE * 4)       // 33536
#define SMEM_TOTAL  (SM_BUF + 2 * BUFSTRIDE)          // 61696 (needs attr > 48K)

// ---------------------------------------------------------------------------
static __device__ __forceinline__ uint32_t bf16x2_rn(float lo, float hi) {
    uint32_t r;
    asm("cvt.rn.bf16x2.f32 %0, %1, %2;" : "=r"(r) : "f"(hi), "f"(lo));
    return r;
}
static __device__ __forceinline__ float bf16_lo_f(uint32_t u) {
    return __uint_as_float(u << 16);
}
static __device__ __forceinline__ float bf16_hi_f(uint32_t u) {
    return __uint_as_float(u & 0xffff0000u);
}
// fp32 pair -> 2 bf16 planes {b1, b2}
static __device__ __forceinline__ uint2 split_pair(float x, float y) {
    uint32_t b1 = bf16x2_rn(x, y);
    float r1x = x - bf16_lo_f(b1);
    float r1y = y - bf16_hi_f(b1);
    uint32_t b2 = bf16x2_rn(r1x, r1y);
    return make_uint2(b1, b2);
}
static __device__ __forceinline__ uint4 pack4(const float4& v) {
    uint2 p0 = split_pair(v.x, v.y);
    uint2 p1 = split_pair(v.z, v.w);
    return make_uint4(p0.x, p0.y, p1.x, p1.y);
}
static __device__ __forceinline__ uint2 lds_pair(const char* base, int row, int p) {
    return *(const uint2*)(base + row * ROWB + p * 8);
}
static __device__ __forceinline__ void mma_bf16(float* d,
                                                uint32_t a0, uint32_t a1,
                                                uint32_t a2, uint32_t a3,
                                                uint32_t b0, uint32_t b1) {
    asm volatile(
        "mma.sync.aligned.m16n8k16.row.col.f32.bf16.bf16.f32 "
        "{%0,%1,%2,%3}, {%4,%5,%6,%7}, {%8,%9}, {%0,%1,%2,%3};"
        : "+f"(d[0]), "+f"(d[1]), "+f"(d[2]), "+f"(d[3])
        : "r"(a0), "r"(a1), "r"(a2), "r"(a3), "r"(b0), "r"(b1));
}

// ---------------------------------------------------------------------------
// Fused: bf16x3 split GEMM (double-buffered, BM=128) + top-4 gap test +
// in-CTA fp64 refinement. One kernel, no global scratch.
// ---------------------------------------------------------------------------
__global__ __launch_bounds__(THREADS)
void router_fused(const float* __restrict__ X, const float* __restrict__ W,
                  const float* __restrict__ bias, float* __restrict__ out) {
    extern __shared__ __align__(16) char smem[];
    float* bias_s = (float*)(smem + SM_BIAS);
    char*  bufs   = smem + SM_BUF;

    const int tid  = threadIdx.x;
    const int wid  = tid >> 5;
    const int lane = tid & 31;
    const int grp  = lane >> 2;     // 0..7
    const int qid  = lane & 3;      // 0..3
    const int token0 = blockIdx.x * BM;
    const int r0 = wid * 16 + grp;  // warp tile: 16 tokens x 64 experts

    // per-thread load slots
    const int tA[4] = { (0*THREADS+tid)>>3, (1*THREADS+tid)>>3,
                        (2*THREADS+tid)>>3, (3*THREADS+tid)>>3 };
    const int eB[2] = { (0*THREADS+tid)>>3, (1*THREADS+tid)>>3 };
    const int kq = tid & 7;

    if (tid < NUM_EXPERTS) bias_s[tid] = bias[tid];

    float acc[8][4];
    #pragma unroll
    for (int n = 0; n < 8; n++)
        #pragma unroll
        for (int r = 0; r < 4; r++) acc[n][r] = 0.0f;

    float4 xa[4], xb[2];
    // prologue: chunk 0 -> buf0 ; chunk 1 -> regs
    #pragma unroll
    for (int r = 0; r < 4; r++)
        xa[r] = *(const float4*)(X + (size_t)(token0 + tA[r]) * D_MODEL + kq * 4);
    #pragma unroll
    for (int r = 0; r < 2; r++)
        xb[r] = *(const float4*)(W + (size_t)eB[r] * D_MODEL + kq * 4);
    #pragma unroll
    for (int r = 0; r < 4; r++)
        *(uint4*)(bufs + tA[r] * ROWB + kq * 16) = pack4(xa[r]);
    #pragma unroll
    for (int r = 0; r < 2; r++)
        *(uint4*)(bufs + ASIZE + eB[r] * ROWB + kq * 16) = pack4(xb[r]);
    #pragma unroll
    for (int r = 0; r < 4; r++)
        xa[r] = *(const float4*)(X + (size_t)(token0 + tA[r]) * D_MODEL + BK + kq * 4);
    #pragma unroll
    for (int r = 0; r < 2; r++)
        xb[r] = *(const float4*)(W + (size_t)eB[r] * D_MODEL + BK + kq * 4);
    __syncthreads();

    #pragma unroll 1
    for (int c = 0; c < NCHUNK; c++) {
        char* cur = bufs + (c & 1) * BUFSTRIDE;
        char* nxt = bufs + ((c + 1) & 1) * BUFSTRIDE;

        // store chunk c+1 (regs) into idle buffer
        if (c + 1 < NCHUNK) {
            #pragma unroll
            for (int r = 0; r < 4; r++)
                *(uint4*)(nxt + tA[r] * ROWB + kq * 16) = pack4(xa[r]);
            #pragma unroll
            for (int r = 0; r < 2; r++)
                *(uint4*)(nxt + ASIZE + eB[r] * ROWB + kq * 16) = pack4(xb[r]);
        }
        // prefetch chunk c+2
        if (c + 2 < NCHUNK) {
            const int k0 = (c + 2) * BK;
            #pragma unroll
            for (int r = 0; r < 4; r++)
                xa[r] = *(const float4*)(X + (size_t)(token0 + tA[r]) * D_MODEL + k0 + kq * 4);
            #pragma unroll
            for (int r = 0; r < 2; r++)
                xb[r] = *(const float4*)(W + (size_t)eB[r] * D_MODEL + k0 + kq * 4);
        }

        // compute chunk c: 2 k16 slices x 8 ntiles x 3 split terms
        const char* As = cur;
        const char* Bs = cur + ASIZE;
        #pragma unroll
        for (int s = 0; s < 2; s++) {
            const int p0 = s * 8 + qid;
            uint2 a0 = lds_pair(As, r0,     p0);
            uint2 a1 = lds_pair(As, r0 + 8, p0);
            uint2 a2 = lds_pair(As, r0,     p0 + 4);
            uint2 a3 = lds_pair(As, r0 + 8, p0 + 4);
            #pragma unroll
            for (int n = 0; n < 8; n++) {
                const int e = n * 8 + grp;
                uint2 b0 = lds_pair(Bs, e, p0);
                uint2 b1 = lds_pair(Bs, e, p0 + 4);
                mma_bf16(acc[n], a0.x, a1.x, a2.x, a3.x, b0.x, b1.x); // 1*1
                mma_bf16(acc[n], a0.x, a1.x, a2.x, a3.x, b0.y, b1.y); // 1*2
                mma_bf16(acc[n], a0.y, a1.y, a2.y, a3.y, b0.x, b1.x); // 2*1
            }
        }
        __syncthreads();
    }

    // ------------------------------------------------------------------
    // epilogue: stage logits, per-token top-4 scan, gap test
    // ------------------------------------------------------------------
    float* L     = (float*)(smem + SM_BUF);      // L[t][e] at t*LSTRIDE+e
    int*   flags = (int*)(smem + SM_FLAGS);      // [0]=count, then 5 ints/record

    #pragma unroll
    for (int n = 0; n < 8; n++) {
        int e0 = n * 8 + 2 * qid;
        L[r0 * LSTRIDE + e0]           = acc[n][0];
        L[r0 * LSTRIDE + e0 + 1]       = acc[n][1];
        L[(r0 + 8) * LSTRIDE + e0]     = acc[n][2];
        L[(r0 + 8) * LSTRIDE + e0 + 1] = acc[n][3];
    }
    if (tid == 0) flags[0] = 0;
    __syncthreads();

    if (tid < BM) {
        const float* Lr = L + tid * LSTRIDE;
        float tv0 = -1e30f, tv1 = -1e30f, tv2 = -1e30f, tv3 = -1e30f;
        int   ti0 = 0, ti1 = 0, ti2 = 0, ti3 = 0;
        #pragma unroll
        for (int e = 0; e < NUM_EXPERTS; e++) {
            float v = Lr[e] + bias_s[e];
            if (v > tv0) {
                tv3 = tv2; ti3 = ti2; tv2 = tv1; ti2 = ti1;
                tv1 = tv0; ti1 = ti0; tv0 = v;  ti0 = e;
            } else if (v > tv1) {
                tv3 = tv2; ti3 = ti2; tv2 = tv1; ti2 = ti1; tv1 = v; ti1 = e;
            } else if (v > tv2) {
                tv3 = tv2; ti3 = ti2; tv2 = v;  ti2 = e;
            } else if (v > tv3) {
                tv3 = v; ti3 = e;
            }
        }
        const int token = token0 + tid;
        if ((tv0 - tv1) < GAP_THRESH || (tv1 - tv2) < GAP_THRESH) {
            int idx = atomicAdd(&flags[0], 1);
            int* rec = &flags[1 + idx * 5];
            rec[0] = token; rec[1] = ti0; rec[2] = ti1; rec[3] = ti2; rec[4] = ti3;
        } else {
            float r  = expf(tv1 - tv0);
            out[token * 2 + 0] = 1.0f / (1.0f + r);
            out[token * 2 + 1] = r / (1.0f + r);
            out[N_TOKENS * 2 + token * 2 + 0] = (float)ti0;
            out[N_TOKENS * 2 + token * 2 + 1] = (float)ti1;
        }
    }
    __syncthreads();

    // ------------------------------------------------------------------
    // in-CTA fp64 refinement of flagged tokens (one warp per record)
    // ------------------------------------------------------------------
    const int nrec = flags[0];
    for (int r = wid; r < nrec; r += 8) {
        const int* rec = &flags[1 + r * 5];
        const int token = rec[0];
        const float* xr = X + (size_t)token * D_MODEL;
        const float* w0 = W + (size_t)rec[1] * D_MODEL;
        const float* w1 = W + (size_t)rec[2] * D_MODEL;
        const float* w2 = W + (size_t)rec[3] * D_MODEL;
        const float* w3 = W + (size_t)rec[4] * D_MODEL;

        double a0[4] = {0, 0, 0, 0}, a1[4] = {0, 0, 0, 0};
        #pragma unroll 4
        for (int k = lane; k < D_MODEL; k += 64) {
            double x0 = (double)xr[k], x1 = (double)xr[k + 32];
            a0[0] += x0 * (double)w0[k];  a1[0] += x1 * (double)w0[k + 32];
            a0[1] += x0 * (double)w1[k];  a1[1] += x1 * (double)w1[k + 32];
            a0[2] += x0 * (double)w2[k];  a1[2] += x1 * (double)w2[k + 32];
            a0[3] += x0 * (double)w3[k];  a1[3] += x1 * (double)w3[k + 32];
        }
        double lv[4];
        #pragma unroll
        for (int cc = 0; cc < 4; cc++) {
            double s = a0[cc] + a1[cc];
            #pragma unroll
            for (int off = 16; off; off >>= 1)
                s += __shfl_down_sync(0xffffffffu, s, off);
            lv[cc] = s + (double)bias_s[rec[1 + cc]];
        }
        if (lane == 0) {
            int ei[4] = {rec[1], rec[2], rec[3], rec[4]};
            #pragma unroll
            for (int i = 1; i < 4; i++) {        // insertion sort desc, tie->lower idx
                double v = lv[i]; int id = ei[i];
                int j = i - 1;
                while (j >= 0 && (lv[j] < v || (lv[j] == v && ei[j] > id))) {
                    lv[j + 1] = lv[j]; ei[j + 1] = ei[j]; j--;
                }
                lv[j + 1] = v; ei[j + 1] = id;
            }
            double rr = exp(lv[1] - lv[0]);
            out[token * 2 + 0] = (float)(1.0 / (1.0 + rr));
            out[token * 2 + 1] = (float)(rr / (1.0 + rr));
            out[N_TOKENS * 2 + token * 2 + 0] = (float)ei[0];
            out[N_TOKENS * 2 + token * 2 + 1] = (float)ei[1];
        }
    }
}

// ---------------------------------------------------------------------------
extern "C" void kernel_launch(void* const* d_in, const int* in_sizes, int n_in,
                              void* d_out, int out_size) {
    const float* X = (const float*)d_in[0];   // [4, 4096, 2048]
    const float* W = (const float*)d_in[1];   // [64, 2048]
    const float* b = (const float*)d_in[2];   // [64]
    float* out = (float*)d_out;

    static int configured = 0;
    if (!configured) {
        cudaFuncSetAttribute(router_fused,
                             cudaFuncAttributeMaxDynamicSharedMemorySize, SMEM_TOTAL);
        configured = 1;
    }
    router_fused<<<N_TOKENS / BM, THREADS, SMEM_TOTAL>>>(X, W, b, out);
}